// round 1
// baseline (speedup 1.0000x reference)
#include <cuda_runtime.h>
#include <cstdint>

#define BSZ  1024
#define TT   32
#define AD   224
#define HID  256
#define VOCAB 29
#define OUT_LEN 25

// ---------------- scratch (device globals; no runtime allocation) ----------------
__device__ float g_y1[BSZ*4*192*28];      // after conv1+pool
__device__ float g_y2[BSZ*16*96*14];      // after conv2+pool
__device__ float g_y3[BSZ*16*32*7];       // after conv3+pool
__device__ float g_y5[BSZ*TT*AD];         // conv4 output reshaped (B,T,AD)
__device__ float g_xW[BSZ*TT*4*AD];       // precomputed y5 @ lstm_Wih^T  (B*T, 896)
__device__ float g_h [BSZ*AD];
__device__ float g_c [BSZ*AD];
__device__ float g_hW[BSZ*4*AD];          // h @ lstm_Whh^T per step
__device__ float g_y8[BSZ*TT*AD];         // encoder hidden states
__device__ float g_escore[BSZ*TT];
__device__ float g_dh[BSZ*HID];
__device__ float g_dc[BSZ*HID];
__device__ float g_ctx[BSZ*AD];
__device__ float g_gates[BSZ*4*HID];

__device__ __forceinline__ float sigm(float x){ return 1.0f/(1.0f+expf(-x)); }

// ---------------- fused conv3x3(pad1)+bias+relu+maxpool ----------------
template<int IC,int OC,int HI,int WI,int PH,int PW,bool Y5OUT>
__global__ void convpool_k(const float* __restrict__ in, const float* __restrict__ wgt,
                           const float* __restrict__ bias, float* __restrict__ out){
    constexpr int HO = HI/PH, WO = WI/PW;
    int idx = blockIdx.x*blockDim.x + threadIdx.x;
    if(idx >= BSZ*OC*HO*WO) return;
    int wo = idx % WO; int t = idx/WO;
    int ho = t % HO;  t /= HO;
    int oc = t % OC;  int b = t/OC;
    const float* ip0 = in + (size_t)b*IC*HI*WI;
    const float* wp0 = wgt + oc*IC*9;
    float bv = __ldg(bias+oc);
    float m = -3.4e38f;
    #pragma unroll
    for(int dh=0; dh<PH; dh++){
        #pragma unroll
        for(int dw=0; dw<PW; dw++){
            int hc = ho*PH+dh, wc = wo*PW+dw;
            float s = bv;
            #pragma unroll 4
            for(int ic=0; ic<IC; ic++){
                const float* ip = ip0 + ic*HI*WI;
                const float* wp = wp0 + ic*9;
                #pragma unroll
                for(int kh=0; kh<3; kh++){
                    int ih = hc+kh-1;
                    if((unsigned)ih < (unsigned)HI){
                        #pragma unroll
                        for(int kw=0; kw<3; kw++){
                            int iw = wc+kw-1;
                            if((unsigned)iw < (unsigned)WI)
                                s += __ldg(ip + ih*WI + iw) * __ldg(wp + kh*3+kw);
                        }
                    }
                }
            }
            s = fmaxf(s, 0.0f);
            m = fmaxf(m, s);
        }
    }
    if(Y5OUT){
        // y5[b][ho][wo*OC + oc]  (transpose NCHW -> N,H,(W,C))
        out[((size_t)b*HO + ho)*(WO*OC) + wo*OC + oc] = m;
    } else {
        out[idx] = m;
    }
}

// ---------------- tiled fp32 GEMM: C[M,N] (+)= A[M,K] * W[N,K]^T ----------------
// M%64==0, N%64==0, K%16==0 required (true for all call sites).
__global__ void gemm64(const float* __restrict__ A, const float* __restrict__ W,
                       float* __restrict__ C, int M, int N, int K, int accumulate){
    __shared__ float As[16][65];
    __shared__ float Ws[16][65];
    int tid = threadIdx.x;              // 256 threads
    int m0 = blockIdx.y*64, n0 = blockIdx.x*64;
    int ty = tid>>4, tx = tid&15;       // 16x16 thread grid, 4x4 per thread
    int mm = tid>>2;                    // 0..63 (load row)
    int kq = (tid&3)*4;                 // 0,4,8,12 (load col group)
    float acc[4][4];
    #pragma unroll
    for(int i=0;i<4;i++)
        #pragma unroll
        for(int j=0;j<4;j++) acc[i][j]=0.f;

    for(int k0=0; k0<K; k0+=16){
        float4 av = *(const float4*)(A + (size_t)(m0+mm)*K + k0 + kq);
        float4 wv = *(const float4*)(W + (size_t)(n0+mm)*K + k0 + kq);
        As[kq+0][mm]=av.x; As[kq+1][mm]=av.y; As[kq+2][mm]=av.z; As[kq+3][mm]=av.w;
        Ws[kq+0][mm]=wv.x; Ws[kq+1][mm]=wv.y; Ws[kq+2][mm]=wv.z; Ws[kq+3][mm]=wv.w;
        __syncthreads();
        #pragma unroll
        for(int kk=0; kk<16; kk++){
            float a0=As[kk][ty*4+0], a1=As[kk][ty*4+1], a2=As[kk][ty*4+2], a3=As[kk][ty*4+3];
            float w0=Ws[kk][tx*4+0], w1=Ws[kk][tx*4+1], w2=Ws[kk][tx*4+2], w3=Ws[kk][tx*4+3];
            acc[0][0]+=a0*w0; acc[0][1]+=a0*w1; acc[0][2]+=a0*w2; acc[0][3]+=a0*w3;
            acc[1][0]+=a1*w0; acc[1][1]+=a1*w1; acc[1][2]+=a1*w2; acc[1][3]+=a1*w3;
            acc[2][0]+=a2*w0; acc[2][1]+=a2*w1; acc[2][2]+=a2*w2; acc[2][3]+=a2*w3;
            acc[3][0]+=a3*w0; acc[3][1]+=a3*w1; acc[3][2]+=a3*w2; acc[3][3]+=a3*w3;
        }
        __syncthreads();
    }
    #pragma unroll
    for(int i=0;i<4;i++){
        size_t m = m0 + ty*4 + i;
        #pragma unroll
        for(int j=0;j<4;j++){
            size_t n = n0 + tx*4 + j;
            float v = acc[i][j];
            if(accumulate) v += C[m*N + n];
            C[m*N + n] = v;
        }
    }
}

// ---------------- encoder LSTM pointwise ----------------
__global__ void enc_pw_k(const float* __restrict__ bih, const float* __restrict__ bhh, int t){
    int idx = blockIdx.x*blockDim.x + threadIdx.x;
    if(idx >= BSZ*AD) return;
    int j = idx % AD, b = idx / AD;
    const float* xw = g_xW + ((size_t)b*TT + t)*(4*AD);
    const float* hw = g_hW + (size_t)b*(4*AD);
    float gi = xw[j       ] + hw[j       ] + __ldg(bih+j       ) + __ldg(bhh+j       );
    float gf = xw[j+  AD  ] + hw[j+  AD  ] + __ldg(bih+j+  AD  ) + __ldg(bhh+j+  AD  );
    float gg = xw[j+2*AD  ] + hw[j+2*AD  ] + __ldg(bih+j+2*AD  ) + __ldg(bhh+j+2*AD  );
    float go = xw[j+3*AD  ] + hw[j+3*AD  ] + __ldg(bih+j+3*AD  ) + __ldg(bhh+j+3*AD  );
    float c = sigm(gf)*g_c[idx] + sigm(gi)*tanhf(gg);
    float h = sigm(go)*tanhf(c);
    g_c[idx] = c; g_h[idx] = h;
    g_y8[((size_t)b*TT + t)*AD + j] = h;
}

__global__ void init_enc_k(const float* __restrict__ h0, const float* __restrict__ c0){
    int idx = blockIdx.x*blockDim.x + threadIdx.x;
    if(idx >= BSZ*AD) return;
    g_h[idx] = __ldg(h0 + idx%AD);
    g_c[idx] = __ldg(c0 + idx%AD);
}

__global__ void init_dec_k(){
    int idx = blockIdx.x*blockDim.x + threadIdx.x;
    if(idx >= BSZ*HID) return;
    g_dh[idx] = 0.f; g_dc[idx] = 0.f;
}

// ---------------- enc_score = y8 @ w_e ----------------
__global__ void enc_score_k(const float* __restrict__ att_w){
    int gl = blockIdx.x*blockDim.x + threadIdx.x;
    int row = gl >> 5, lane = gl & 31;
    if(row >= BSZ*TT) return;
    const float* r = g_y8 + (size_t)row*AD;
    const float* we = att_w + HID;
    float s = 0.f;
    for(int k=lane; k<AD; k+=32) s += r[k]*__ldg(we+k);
    #pragma unroll
    for(int o=16;o>0;o>>=1) s += __shfl_xor_sync(0xffffffffu, s, o);
    if(lane==0) g_escore[row] = s;
}

// ---------------- attention: softmax over T + context ----------------
__global__ void attn_k(const float* __restrict__ att_w, const float* __restrict__ att_b){
    int b = blockIdx.x, tid = threadIdx.x;   // 256 threads
    __shared__ float red[256];
    __shared__ float sc[TT];
    float v = (tid<HID) ? g_dh[(size_t)b*HID + tid]*__ldg(att_w+tid) : 0.f;
    red[tid] = v; __syncthreads();
    #pragma unroll
    for(int s=128;s>0;s>>=1){ if(tid<s) red[tid]+=red[tid+s]; __syncthreads(); }
    float hw = red[0] + __ldg(att_b);
    if(tid < TT) sc[tid] = g_escore[b*TT + tid] + hw;
    __syncthreads();
    if(tid < 32){
        float x = sc[tid];
        float mx = x;
        #pragma unroll
        for(int o=16;o>0;o>>=1) mx = fmaxf(mx, __shfl_xor_sync(0xffffffffu, mx, o));
        float e = expf(x - mx);
        float sm = e;
        #pragma unroll
        for(int o=16;o>0;o>>=1) sm += __shfl_xor_sync(0xffffffffu, sm, o);
        sc[tid] = e/sm;
    }
    __syncthreads();
    if(tid < AD){
        const float* y = g_y8 + (size_t)b*TT*AD + tid;
        float s = 0.f;
        #pragma unroll
        for(int t=0;t<TT;t++) s += sc[t]*y[t*AD];
        g_ctx[(size_t)b*AD + tid] = s;
    }
}

// ---------------- decoder LSTM pointwise ----------------
__global__ void dec_pw_k(const float* __restrict__ bih, const float* __restrict__ bhh){
    int idx = blockIdx.x*blockDim.x + threadIdx.x;
    if(idx >= BSZ*HID) return;
    int j = idx % HID, b = idx / HID;
    const float* g = g_gates + (size_t)b*4*HID;
    float gi = g[j        ] + __ldg(bih+j        ) + __ldg(bhh+j        );
    float gf = g[j+  HID  ] + __ldg(bih+j+  HID  ) + __ldg(bhh+j+  HID  );
    float gg = g[j+2*HID  ] + __ldg(bih+j+2*HID  ) + __ldg(bhh+j+2*HID  );
    float go = g[j+3*HID  ] + __ldg(bih+j+3*HID  ) + __ldg(bhh+j+3*HID  );
    float c = sigm(gf)*g_dc[idx] + sigm(gi)*tanhf(gg);
    float h = sigm(go)*tanhf(c);
    g_dc[idx] = c; g_dh[idx] = h;
}

// ---------------- output projection (one warp per (b,v)) ----------------
__global__ void out_k(const float* __restrict__ out_w, const float* __restrict__ out_b,
                      float* __restrict__ out, int step){
    int gl = blockIdx.x*blockDim.x + threadIdx.x;
    int wid = gl >> 5, lane = gl & 31;
    if(wid >= BSZ*VOCAB) return;
    int v = wid % VOCAB, b = wid / VOCAB;
    const float* h = g_dh + (size_t)b*HID;
    const float* w = out_w + (size_t)v*HID;
    float s = 0.f;
    #pragma unroll
    for(int k=lane; k<HID; k+=32) s += h[k]*__ldg(w+k);
    #pragma unroll
    for(int o=16;o>0;o>>=1) s += __shfl_xor_sync(0xffffffffu, s, o);
    if(lane==0) out[(size_t)b*VOCAB*OUT_LEN + v*OUT_LEN + step] = s + __ldg(out_b+v);
}

// ---------------- launch ----------------
extern "C" void kernel_launch(void* const* d_in, const int* in_sizes, int n_in,
                              void* d_out, int out_size){
    const float* x       = (const float*)d_in[0];
    const float* c1w     = (const float*)d_in[1];
    const float* c1b     = (const float*)d_in[2];
    const float* c2w     = (const float*)d_in[3];
    const float* c2b     = (const float*)d_in[4];
    const float* c3w     = (const float*)d_in[5];
    const float* c3b     = (const float*)d_in[6];
    const float* c4w     = (const float*)d_in[7];
    const float* c4b     = (const float*)d_in[8];
    const float* h0      = (const float*)d_in[9];
    const float* c0      = (const float*)d_in[10];
    const float* lstmWih = (const float*)d_in[11];
    const float* lstmWhh = (const float*)d_in[12];
    const float* lstmbih = (const float*)d_in[13];
    const float* lstmbhh = (const float*)d_in[14];
    const float* attw    = (const float*)d_in[15];
    const float* attb    = (const float*)d_in[16];
    const float* decWih  = (const float*)d_in[17];
    const float* decWhh  = (const float*)d_in[18];
    const float* decbih  = (const float*)d_in[19];
    const float* decbhh  = (const float*)d_in[20];
    const float* outw    = (const float*)d_in[21];
    const float* outb    = (const float*)d_in[22];
    float* out = (float*)d_out;

    float *y1,*y2,*y3,*y5,*xW,*h,*hW,*dh,*ctx,*gates;
    cudaGetSymbolAddress((void**)&y1,    g_y1);
    cudaGetSymbolAddress((void**)&y2,    g_y2);
    cudaGetSymbolAddress((void**)&y3,    g_y3);
    cudaGetSymbolAddress((void**)&y5,    g_y5);
    cudaGetSymbolAddress((void**)&xW,    g_xW);
    cudaGetSymbolAddress((void**)&h,     g_h);
    cudaGetSymbolAddress((void**)&hW,    g_hW);
    cudaGetSymbolAddress((void**)&dh,    g_dh);
    cudaGetSymbolAddress((void**)&ctx,   g_ctx);
    cudaGetSymbolAddress((void**)&gates, g_gates);

    // conv stack (fused conv+relu+pool)
    convpool_k<1, 4,384,28,2,1,false><<<(BSZ*4*192*28+255)/256,256>>>(x,  c1w,c1b, y1);
    convpool_k<4,16,192,28,2,2,false><<<(BSZ*16*96*14+255)/256,256>>>(y1, c2w,c2b, y2);
    convpool_k<16,16, 96,14,3,2,false><<<(BSZ*16*32*7+255)/256,256>>>(y2, c3w,c3b, y3);
    convpool_k<16,32, 32, 7,1,1,true ><<<(BSZ*32*32*7+255)/256,256>>>(y3, c4w,c4b, y5);

    // hoisted encoder input transform: (B*T,224) @ (896,224)^T
    gemm64<<<dim3(4*AD/64, BSZ*TT/64), 256>>>(y5, lstmWih, xW, BSZ*TT, 4*AD, AD, 0);

    // encoder LSTM scan
    init_enc_k<<<(BSZ*AD+255)/256,256>>>(h0, c0);
    for(int t=0; t<TT; t++){
        gemm64<<<dim3(4*AD/64, BSZ/64), 256>>>(h, lstmWhh, hW, BSZ, 4*AD, AD, 0);
        enc_pw_k<<<(BSZ*AD+255)/256,256>>>(lstmbih, lstmbhh, t);
    }

    // attention precompute + decoder init
    enc_score_k<<<(BSZ*TT*32+255)/256,256>>>(attw);
    init_dec_k<<<(BSZ*HID+255)/256,256>>>();

    // decoder scan
    for(int s=0; s<OUT_LEN; s++){
        attn_k<<<BSZ,256>>>(attw, attb);
        gemm64<<<dim3(4*HID/64, BSZ/64), 256>>>(ctx, decWih, gates, BSZ, 4*HID, AD,  0);
        gemm64<<<dim3(4*HID/64, BSZ/64), 256>>>(dh,  decWhh, gates, BSZ, 4*HID, HID, 1);
        dec_pw_k<<<(BSZ*HID+255)/256,256>>>(decbih, decbhh);
        out_k<<<(BSZ*VOCAB*32+255)/256,256>>>(outw, outb, out, s);
    }
}

// round 2
// speedup vs baseline: 1.0038x; 1.0038x over previous
#include <cuda_runtime.h>
#include <cstdint>

#define BSZ  1024
#define TT   32
#define AD   224
#define HID  256
#define VOCAB 29
#define OUT_LEN 25

// ---------------- scratch (device globals; no runtime allocation) ----------------
__device__ float g_y1[BSZ*4*192*28];      // after conv1+pool
__device__ float g_y2[BSZ*16*96*14];      // after conv2+pool
__device__ float g_y3[BSZ*16*32*7];       // after conv3+pool
__device__ float g_y5[BSZ*TT*AD];         // conv4 output reshaped (B,T,AD)
__device__ float g_xW[BSZ*TT*4*AD];       // precomputed y5 @ lstm_Wih^T  (B*T, 896)
__device__ float g_h [BSZ*AD];
__device__ float g_c [BSZ*AD];
__device__ float g_hW[BSZ*4*AD];          // h @ lstm_Whh^T per step
__device__ float g_y8[BSZ*TT*AD];         // encoder hidden states
__device__ float g_escore[BSZ*TT];
__device__ float g_dh[BSZ*HID];
__device__ float g_dc[BSZ*HID];
__device__ float g_ctx[BSZ*AD];
__device__ float g_gates[BSZ*4*HID];

__device__ __forceinline__ float sigm(float x){ return 1.0f/(1.0f+expf(-x)); }

// ---------------- fused conv3x3(pad1)+bias+relu+maxpool ----------------
template<int IC,int OC,int HI,int WI,int PH,int PW,bool Y5OUT>
__global__ void convpool_k(const float* __restrict__ in, const float* __restrict__ wgt,
                           const float* __restrict__ bias, float* __restrict__ out){
    constexpr int HO = HI/PH, WO = WI/PW;
    int idx = blockIdx.x*blockDim.x + threadIdx.x;
    if(idx >= BSZ*OC*HO*WO) return;
    int wo = idx % WO; int t = idx/WO;
    int ho = t % HO;  t /= HO;
    int oc = t % OC;  int b = t/OC;
    const float* ip0 = in + (size_t)b*IC*HI*WI;
    const float* wp0 = wgt + oc*IC*9;
    float bv = __ldg(bias+oc);
    float m = -3.4e38f;
    #pragma unroll
    for(int dh=0; dh<PH; dh++){
        #pragma unroll
        for(int dw=0; dw<PW; dw++){
            int hc = ho*PH+dh, wc = wo*PW+dw;
            float s = bv;
            #pragma unroll 4
            for(int ic=0; ic<IC; ic++){
                const float* ip = ip0 + ic*HI*WI;
                const float* wp = wp0 + ic*9;
                #pragma unroll
                for(int kh=0; kh<3; kh++){
                    int ih = hc+kh-1;
                    if((unsigned)ih < (unsigned)HI){
                        #pragma unroll
                        for(int kw=0; kw<3; kw++){
                            int iw = wc+kw-1;
                            if((unsigned)iw < (unsigned)WI)
                                s += __ldg(ip + ih*WI + iw) * __ldg(wp + kh*3+kw);
                        }
                    }
                }
            }
            s = fmaxf(s, 0.0f);
            m = fmaxf(m, s);
        }
    }
    if(Y5OUT){
        // y5[b][ho][wo*OC + oc]  (transpose NCHW -> N,H,(W,C))
        out[((size_t)b*HO + ho)*(WO*OC) + wo*OC + oc] = m;
    } else {
        out[idx] = m;
    }
}

// ---------------- tiled fp32 GEMM: C[M,N] (+)= A[M,K] * W[N,K]^T ----------------
// M%64==0, N%64==0, K%16==0 required (true for all call sites).
__global__ void gemm64(const float* __restrict__ A, const float* __restrict__ W,
                       float* __restrict__ C, int M, int N, int K, int accumulate){
    __shared__ float As[16][65];
    __shared__ float Ws[16][65];
    int tid = threadIdx.x;              // 256 threads
    int m0 = blockIdx.y*64, n0 = blockIdx.x*64;
    int ty = tid>>4, tx = tid&15;       // 16x16 thread grid, 4x4 per thread
    int mm = tid>>2;                    // 0..63 (load row)
    int kq = (tid&3)*4;                 // 0,4,8,12 (load col group)
    float acc[4][4];
    #pragma unroll
    for(int i=0;i<4;i++)
        #pragma unroll
        for(int j=0;j<4;j++) acc[i][j]=0.f;

    for(int k0=0; k0<K; k0+=16){
        float4 av = *(const float4*)(A + (size_t)(m0+mm)*K + k0 + kq);
        float4 wv = *(const float4*)(W + (size_t)(n0+mm)*K + k0 + kq);
        As[kq+0][mm]=av.x; As[kq+1][mm]=av.y; As[kq+2][mm]=av.z; As[kq+3][mm]=av.w;
        Ws[kq+0][mm]=wv.x; Ws[kq+1][mm]=wv.y; Ws[kq+2][mm]=wv.z; Ws[kq+3][mm]=wv.w;
        __syncthreads();
        #pragma unroll
        for(int kk=0; kk<16; kk++){
            float a0=As[kk][ty*4+0], a1=As[kk][ty*4+1], a2=As[kk][ty*4+2], a3=As[kk][ty*4+3];
            float w0=Ws[kk][tx*4+0], w1=Ws[kk][tx*4+1], w2=Ws[kk][tx*4+2], w3=Ws[kk][tx*4+3];
            acc[0][0]+=a0*w0; acc[0][1]+=a0*w1; acc[0][2]+=a0*w2; acc[0][3]+=a0*w3;
            acc[1][0]+=a1*w0; acc[1][1]+=a1*w1; acc[1][2]+=a1*w2; acc[1][3]+=a1*w3;
            acc[2][0]+=a2*w0; acc[2][1]+=a2*w1; acc[2][2]+=a2*w2; acc[2][3]+=a2*w3;
            acc[3][0]+=a3*w0; acc[3][1]+=a3*w1; acc[3][2]+=a3*w2; acc[3][3]+=a3*w3;
        }
        __syncthreads();
    }
    #pragma unroll
    for(int i=0;i<4;i++){
        size_t m = m0 + ty*4 + i;
        #pragma unroll
        for(int j=0;j<4;j++){
            size_t n = n0 + tx*4 + j;
            float v = acc[i][j];
            if(accumulate) v += C[m*N + n];
            C[m*N + n] = v;
        }
    }
}

// ---------------- encoder LSTM pointwise ----------------
__global__ void enc_pw_k(const float* __restrict__ bih, const float* __restrict__ bhh, int t){
    int idx = blockIdx.x*blockDim.x + threadIdx.x;
    if(idx >= BSZ*AD) return;
    int j = idx % AD, b = idx / AD;
    const float* xw = g_xW + ((size_t)b*TT + t)*(4*AD);
    const float* hw = g_hW + (size_t)b*(4*AD);
    float gi = xw[j       ] + hw[j       ] + __ldg(bih+j       ) + __ldg(bhh+j       );
    float gf = xw[j+  AD  ] + hw[j+  AD  ] + __ldg(bih+j+  AD  ) + __ldg(bhh+j+  AD  );
    float gg = xw[j+2*AD  ] + hw[j+2*AD  ] + __ldg(bih+j+2*AD  ) + __ldg(bhh+j+2*AD  );
    float go = xw[j+3*AD  ] + hw[j+3*AD  ] + __ldg(bih+j+3*AD  ) + __ldg(bhh+j+3*AD  );
    float c = sigm(gf)*g_c[idx] + sigm(gi)*tanhf(gg);
    float h = sigm(go)*tanhf(c);
    g_c[idx] = c; g_h[idx] = h;
    g_y8[((size_t)b*TT + t)*AD + j] = h;
}

__global__ void init_enc_k(const float* __restrict__ h0, const float* __restrict__ c0){
    int idx = blockIdx.x*blockDim.x + threadIdx.x;
    if(idx >= BSZ*AD) return;
    g_h[idx] = __ldg(h0 + idx%AD);
    g_c[idx] = __ldg(c0 + idx%AD);
}

__global__ void init_dec_k(){
    int idx = blockIdx.x*blockDim.x + threadIdx.x;
    if(idx >= BSZ*HID) return;
    g_dh[idx] = 0.f; g_dc[idx] = 0.f;
}

// ---------------- enc_score = y8 @ w_e ----------------
__global__ void enc_score_k(const float* __restrict__ att_w){
    int gl = blockIdx.x*blockDim.x + threadIdx.x;
    int row = gl >> 5, lane = gl & 31;
    if(row >= BSZ*TT) return;
    const float* r = g_y8 + (size_t)row*AD;
    const float* we = att_w + HID;
    float s = 0.f;
    for(int k=lane; k<AD; k+=32) s += r[k]*__ldg(we+k);
    #pragma unroll
    for(int o=16;o>0;o>>=1) s += __shfl_xor_sync(0xffffffffu, s, o);
    if(lane==0) g_escore[row] = s;
}

// ---------------- attention: softmax over T + context ----------------
__global__ void attn_k(const float* __restrict__ att_w, const float* __restrict__ att_b){
    int b = blockIdx.x, tid = threadIdx.x;   // 256 threads
    __shared__ float red[256];
    __shared__ float sc[TT];
    float v = (tid<HID) ? g_dh[(size_t)b*HID + tid]*__ldg(att_w+tid) : 0.f;
    red[tid] = v; __syncthreads();
    #pragma unroll
    for(int s=128;s>0;s>>=1){ if(tid<s) red[tid]+=red[tid+s]; __syncthreads(); }
    float hw = red[0] + __ldg(att_b);
    if(tid < TT) sc[tid] = g_escore[b*TT + tid] + hw;
    __syncthreads();
    if(tid < 32){
        float x = sc[tid];
        float mx = x;
        #pragma unroll
        for(int o=16;o>0;o>>=1) mx = fmaxf(mx, __shfl_xor_sync(0xffffffffu, mx, o));
        float e = expf(x - mx);
        float sm = e;
        #pragma unroll
        for(int o=16;o>0;o>>=1) sm += __shfl_xor_sync(0xffffffffu, sm, o);
        sc[tid] = e/sm;
    }
    __syncthreads();
    if(tid < AD){
        const float* y = g_y8 + (size_t)b*TT*AD + tid;
        float s = 0.f;
        #pragma unroll
        for(int t=0;t<TT;t++) s += sc[t]*y[t*AD];
        g_ctx[(size_t)b*AD + tid] = s;
    }
}

// ---------------- decoder LSTM pointwise ----------------
__global__ void dec_pw_k(const float* __restrict__ bih, const float* __restrict__ bhh){
    int idx = blockIdx.x*blockDim.x + threadIdx.x;
    if(idx >= BSZ*HID) return;
    int j = idx % HID, b = idx / HID;
    const float* g = g_gates + (size_t)b*4*HID;
    float gi = g[j        ] + __ldg(bih+j        ) + __ldg(bhh+j        );
    float gf = g[j+  HID  ] + __ldg(bih+j+  HID  ) + __ldg(bhh+j+  HID  );
    float gg = g[j+2*HID  ] + __ldg(bih+j+2*HID  ) + __ldg(bhh+j+2*HID  );
    float go = g[j+3*HID  ] + __ldg(bih+j+3*HID  ) + __ldg(bhh+j+3*HID  );
    float c = sigm(gf)*g_dc[idx] + sigm(gi)*tanhf(gg);
    float h = sigm(go)*tanhf(c);
    g_dc[idx] = c; g_dh[idx] = h;
}

// ---------------- output projection (one warp per (b,v)) ----------------
__global__ void out_k(const float* __restrict__ out_w, const float* __restrict__ out_b,
                      float* __restrict__ out, int step){
    int gl = blockIdx.x*blockDim.x + threadIdx.x;
    int wid = gl >> 5, lane = gl & 31;
    if(wid >= BSZ*VOCAB) return;
    int v = wid % VOCAB, b = wid / VOCAB;
    const float* h = g_dh + (size_t)b*HID;
    const float* w = out_w + (size_t)v*HID;
    float s = 0.f;
    #pragma unroll
    for(int k=lane; k<HID; k+=32) s += h[k]*__ldg(w+k);
    #pragma unroll
    for(int o=16;o>0;o>>=1) s += __shfl_xor_sync(0xffffffffu, s, o);
    if(lane==0) out[(size_t)b*VOCAB*OUT_LEN + v*OUT_LEN + step] = s + __ldg(out_b+v);
}

// ---------------- launch ----------------
extern "C" void kernel_launch(void* const* d_in, const int* in_sizes, int n_in,
                              void* d_out, int out_size){
    const float* x       = (const float*)d_in[0];
    const float* c1w     = (const float*)d_in[1];
    const float* c1b     = (const float*)d_in[2];
    const float* c2w     = (const float*)d_in[3];
    const float* c2b     = (const float*)d_in[4];
    const float* c3w     = (const float*)d_in[5];
    const float* c3b     = (const float*)d_in[6];
    const float* c4w     = (const float*)d_in[7];
    const float* c4b     = (const float*)d_in[8];
    const float* h0      = (const float*)d_in[9];
    const float* c0      = (const float*)d_in[10];
    const float* lstmWih = (const float*)d_in[11];
    const float* lstmWhh = (const float*)d_in[12];
    const float* lstmbih = (const float*)d_in[13];
    const float* lstmbhh = (const float*)d_in[14];
    const float* attw    = (const float*)d_in[15];
    const float* attb    = (const float*)d_in[16];
    const float* decWih  = (const float*)d_in[17];
    const float* decWhh  = (const float*)d_in[18];
    const float* decbih  = (const float*)d_in[19];
    const float* decbhh  = (const float*)d_in[20];
    const float* outw    = (const float*)d_in[21];
    const float* outb    = (const float*)d_in[22];
    float* out = (float*)d_out;

    float *y1,*y2,*y3,*y5,*xW,*h,*hW,*dh,*ctx,*gates;
    cudaGetSymbolAddress((void**)&y1,    g_y1);
    cudaGetSymbolAddress((void**)&y2,    g_y2);
    cudaGetSymbolAddress((void**)&y3,    g_y3);
    cudaGetSymbolAddress((void**)&y5,    g_y5);
    cudaGetSymbolAddress((void**)&xW,    g_xW);
    cudaGetSymbolAddress((void**)&h,     g_h);
    cudaGetSymbolAddress((void**)&hW,    g_hW);
    cudaGetSymbolAddress((void**)&dh,    g_dh);
    cudaGetSymbolAddress((void**)&ctx,   g_ctx);
    cudaGetSymbolAddress((void**)&gates, g_gates);

    // conv stack (fused conv+relu+pool)
    convpool_k<1, 4,384,28,2,1,false><<<(BSZ*4*192*28+255)/256,256>>>(x,  c1w,c1b, y1);
    convpool_k<4,16,192,28,2,2,false><<<(BSZ*16*96*14+255)/256,256>>>(y1, c2w,c2b, y2);
    convpool_k<16,16, 96,14,3,2,false><<<(BSZ*16*32*7+255)/256,256>>>(y2, c3w,c3b, y3);
    convpool_k<16,32, 32, 7,1,1,true ><<<(BSZ*32*32*7+255)/256,256>>>(y3, c4w,c4b, y5);

    // hoisted encoder input transform: (B*T,224) @ (896,224)^T
    gemm64<<<dim3(4*AD/64, BSZ*TT/64), 256>>>(y5, lstmWih, xW, BSZ*TT, 4*AD, AD, 0);

    // encoder LSTM scan
    init_enc_k<<<(BSZ*AD+255)/256,256>>>(h0, c0);
    for(int t=0; t<TT; t++){
        gemm64<<<dim3(4*AD/64, BSZ/64), 256>>>(h, lstmWhh, hW, BSZ, 4*AD, AD, 0);
        enc_pw_k<<<(BSZ*AD+255)/256,256>>>(lstmbih, lstmbhh, t);
    }

    // attention precompute + decoder init
    enc_score_k<<<(BSZ*TT*32+255)/256,256>>>(attw);
    init_dec_k<<<(BSZ*HID+255)/256,256>>>();

    // decoder scan
    for(int s=0; s<OUT_LEN; s++){
        attn_k<<<BSZ,256>>>(attw, attb);
        gemm64<<<dim3(4*HID/64, BSZ/64), 256>>>(ctx, decWih, gates, BSZ, 4*HID, AD,  0);
        gemm64<<<dim3(4*HID/64, BSZ/64), 256>>>(dh,  decWhh, gates, BSZ, 4*HID, HID, 1);
        dec_pw_k<<<(BSZ*HID+255)/256,256>>>(decbih, decbhh);
        out_k<<<(BSZ*VOCAB*32+255)/256,256>>>(outw, outb, out, s);
    }
}

// round 3
// speedup vs baseline: 1.2115x; 1.2070x over previous
#include <cuda_runtime.h>
#include <cuda_bf16.h>
#include <cstdint>

#define BSZ  1024
#define TT   32
#define AD   224
#define HID  256
#define VOCAB 29
#define OUT_LEN 25

// ---------------- scratch (device globals; no runtime allocation) ----------------
__device__ float g_y1[BSZ*4*192*28];
__device__ float g_y2[BSZ*16*96*14];
__device__ float g_y3[BSZ*16*32*7];
__device__ float g_y5[BSZ*TT*AD];
__device__ float g_xW[BSZ*TT*4*AD];
__device__ float g_h [BSZ*AD];
__device__ float g_c [BSZ*AD];
__device__ float g_hW[BSZ*4*AD];
__device__ float g_y8[BSZ*TT*AD];
__device__ float g_escore[BSZ*TT];
__device__ float g_dh[BSZ*HID];
__device__ float g_dc[BSZ*HID];
__device__ float g_ctx[BSZ*AD];
__device__ float g_gates[BSZ*4*HID];

__device__ __forceinline__ float sigm(float x){ return 1.0f/(1.0f+expf(-x)); }
__device__ __forceinline__ float4 ffma4(float4 a, float4 x, float4 w){
    a.x = fmaf(x.x,w.x,a.x); a.y = fmaf(x.y,w.y,a.y);
    a.z = fmaf(x.z,w.z,a.z); a.w = fmaf(x.w,w.w,a.w); return a;
}
__device__ __forceinline__ float hsum4(float4 a){ return a.x+a.y+a.z+a.w; }

// ---------------- generic fused conv3x3(pad1)+bias+relu+maxpool (conv1-3) ----------------
template<int IC,int OC,int HI,int WI,int PH,int PW>
__global__ void convpool_k(const float* __restrict__ in, const float* __restrict__ wgt,
                           const float* __restrict__ bias, float* __restrict__ out){
    constexpr int HO = HI/PH, WO = WI/PW;
    int idx = blockIdx.x*blockDim.x + threadIdx.x;
    if(idx >= BSZ*OC*HO*WO) return;
    int wo = idx % WO; int t = idx/WO;
    int ho = t % HO;  t /= HO;
    int oc = t % OC;  int b = t/OC;
    const float* ip0 = in + (size_t)b*IC*HI*WI;
    const float* wp0 = wgt + oc*IC*9;
    float bv = __ldg(bias+oc);
    float m = -3.4e38f;
    #pragma unroll
    for(int dh=0; dh<PH; dh++){
        #pragma unroll
        for(int dw=0; dw<PW; dw++){
            int hc = ho*PH+dh, wc = wo*PW+dw;
            float s = bv;
            #pragma unroll 4
            for(int ic=0; ic<IC; ic++){
                const float* ip = ip0 + ic*HI*WI;
                const float* wp = wp0 + ic*9;
                #pragma unroll
                for(int kh=0; kh<3; kh++){
                    int ih = hc+kh-1;
                    if((unsigned)ih < (unsigned)HI){
                        #pragma unroll
                        for(int kw=0; kw<3; kw++){
                            int iw = wc+kw-1;
                            if((unsigned)iw < (unsigned)WI)
                                s += __ldg(ip + ih*WI + iw) * __ldg(wp + kh*3+kw);
                        }
                    }
                }
            }
            s = fmaxf(s, 0.0f);
            m = fmaxf(m, s);
        }
    }
    out[idx] = m;
}

// ---------------- conv4: IC=16 OC=32, (16,32,7)->(32,32,7), no pool, writes y5 ----------------
__global__ __launch_bounds__(256) void conv4_k(const float* __restrict__ in,
        const float* __restrict__ cw, const float* __restrict__ cb, float* __restrict__ out){
    __shared__ float4 xin[4*34*9];     // [icg][row+pad][col+pad], 4 ic packed
    __shared__ float4 w_s[1152];       // [oc][icg][k]
    __shared__ float  b_s[32];
    int b = blockIdx.x;
    int tid = threadIdx.x, lane = tid & 31, warp = tid >> 5;
    for(int f = tid; f < 4*34*9; f += 256){
        int icg = f/(34*9), rr = (f/9)%34, cc = f%9;
        int gr = rr - 1, gc = cc - 1;
        float4 v = {0,0,0,0};
        if(gr >= 0 && gr < 32 && gc >= 0 && gc < 7){
            const float* p = in + ((size_t)(b*16 + icg*4)*32 + gr)*7 + gc;
            v.x = p[0]; v.y = p[32*7]; v.z = p[2*32*7]; v.w = p[3*32*7];
        }
        xin[f] = v;
    }
    for(int f = tid; f < 1152; f += 256){
        int oc = f/36, icg = (f/9)%4, k = f%9;
        float4 v;
        v.x = cw[(oc*16+icg*4+0)*9+k]; v.y = cw[(oc*16+icg*4+1)*9+k];
        v.z = cw[(oc*16+icg*4+2)*9+k]; v.w = cw[(oc*16+icg*4+3)*9+k];
        w_s[f] = v;
    }
    if(tid < 32) b_s[tid] = cb[tid];
    __syncthreads();
    int quarter = lane >> 3;
    int wc = min(lane & 7, 6);
    for(int ib = warp; ib < 64; ib += 8){
        int item = ib*4 + quarter;          // 0..255 = oc(32) x hq(8)
        int oc = item >> 3, hq = item & 7;
        float4 ac[4] = {{0,0,0,0},{0,0,0,0},{0,0,0,0},{0,0,0,0}};
        #pragma unroll
        for(int icg=0; icg<4; icg++){
            float4 wr[9];
            #pragma unroll
            for(int k=0;k<9;k++) wr[k] = w_s[(oc*4+icg)*9+k];
            #pragma unroll
            for(int kw=0; kw<3; kw++){
                float4 X[6];
                #pragma unroll
                for(int r=0;r<6;r++) X[r] = xin[(icg*34 + 4*hq + r)*9 + wc + kw];
                #pragma unroll
                for(int kh=0;kh<3;kh++){
                    float4 w = wr[kh*3+kw];
                    #pragma unroll
                    for(int r=0;r<4;r++) ac[r] = ffma4(ac[r], X[r+kh], w);
                }
            }
        }
        float bv = b_s[oc];
        #pragma unroll
        for(int r=0;r<4;r++){
            float s = fmaxf(hsum4(ac[r]) + bv, 0.f);
            if((lane & 7) < 7)
                out[((size_t)b*32 + hq*4 + r)*224 + wc*32 + oc] = s;  // y5[b][h][w*32+oc]
        }
    }
}

// =====================================================================
//  bf16x3 tensor-core GEMM: C[M,N] (+)= A[M,K] @ W[N,K]^T
//  block: 128 threads, tile 64x64, k-chunk 32. M,N%64==0, K%32==0.
// =====================================================================
#define SAU 17   // u32 row stride (16 k-pairs + 1 pad)

__device__ __forceinline__ void splitpair(float x, float y, uint32_t& hi, uint32_t& lo){
    __nv_bfloat162 h = __floats2bfloat162_rn(x, y);
    float rx = x - __bfloat162float(h.x);
    float ry = y - __bfloat162float(h.y);
    __nv_bfloat162 l = __floats2bfloat162_rn(rx, ry);
    hi = *reinterpret_cast<uint32_t*>(&h);
    lo = *reinterpret_cast<uint32_t*>(&l);
}

#define MMA(c, a, b) asm volatile( \
    "mma.sync.aligned.m16n8k16.row.col.f32.bf16.bf16.f32 " \
    "{%0,%1,%2,%3},{%4,%5,%6,%7},{%8,%9},{%0,%1,%2,%3};" \
    : "+f"(c[0]),"+f"(c[1]),"+f"(c[2]),"+f"(c[3]) \
    : "r"(a[0]),"r"(a[1]),"r"(a[2]),"r"(a[3]),"r"(b[0]),"r"(b[1]))

__global__ __launch_bounds__(128) void gemm_tc(const float* __restrict__ A,
        const float* __restrict__ W, float* __restrict__ C,
        int M, int N, int K, int accumulate){
    __shared__ uint32_t Ah[64*SAU], Al[64*SAU], Bh[64*SAU], Bl[64*SAU];
    int tid = threadIdx.x;
    int m0 = blockIdx.y*64, n0 = blockIdx.x*64;
    int warp = tid>>5, lane = tid&31;
    int wm = warp>>1, wn = warp&1;      // 2x2 warp grid, 32x32 per warp
    int g = lane>>2, tg = lane&3;

    float acc[2][4][4];
    #pragma unroll
    for(int mi=0;mi<2;mi++)
        #pragma unroll
        for(int ni=0;ni<4;ni++)
            #pragma unroll
            for(int r=0;r<4;r++) acc[mi][ni][r]=0.f;

    int lr = tid>>1;            // load row 0..63
    int lk = (tid&1)*16;        // k offset within chunk
    int lkp = (tid&1)*8;        // k-pair offset

    for(int k0=0; k0<K; k0+=32){
        const float* pa = A + (size_t)(m0+lr)*K + k0 + lk;
        const float* pb = W + (size_t)(n0+lr)*K + k0 + lk;
        #pragma unroll
        for(int q=0;q<4;q++){
            float4 a = *(const float4*)(pa + q*4);
            float4 b = *(const float4*)(pb + q*4);
            uint32_t h0,l0,h1,l1;
            splitpair(a.x,a.y,h0,l0); splitpair(a.z,a.w,h1,l1);
            Ah[lr*SAU + lkp + q*2    ] = h0;  Al[lr*SAU + lkp + q*2    ] = l0;
            Ah[lr*SAU + lkp + q*2 + 1] = h1;  Al[lr*SAU + lkp + q*2 + 1] = l1;
            splitpair(b.x,b.y,h0,l0); splitpair(b.z,b.w,h1,l1);
            Bh[lr*SAU + lkp + q*2    ] = h0;  Bl[lr*SAU + lkp + q*2    ] = l0;
            Bh[lr*SAU + lkp + q*2 + 1] = h1;  Bl[lr*SAU + lkp + q*2 + 1] = l1;
        }
        __syncthreads();
        #pragma unroll
        for(int kk=0;kk<2;kk++){
            uint32_t aH[2][4], aL[2][4], bH[4][2], bL[4][2];
            int kp = kk*8 + tg;
            #pragma unroll
            for(int mi=0;mi<2;mi++){
                int r0 = wm*32 + mi*16 + g;
                aH[mi][0]=Ah[ r0   *SAU+kp  ]; aH[mi][1]=Ah[(r0+8)*SAU+kp  ];
                aH[mi][2]=Ah[ r0   *SAU+kp+4]; aH[mi][3]=Ah[(r0+8)*SAU+kp+4];
                aL[mi][0]=Al[ r0   *SAU+kp  ]; aL[mi][1]=Al[(r0+8)*SAU+kp  ];
                aL[mi][2]=Al[ r0   *SAU+kp+4]; aL[mi][3]=Al[(r0+8)*SAU+kp+4];
            }
            #pragma unroll
            for(int ni=0;ni<4;ni++){
                int c0 = wn*32 + ni*8 + g;
                bH[ni][0]=Bh[c0*SAU+kp]; bH[ni][1]=Bh[c0*SAU+kp+4];
                bL[ni][0]=Bl[c0*SAU+kp]; bL[ni][1]=Bl[c0*SAU+kp+4];
            }
            #pragma unroll
            for(int mi=0;mi<2;mi++)
                #pragma unroll
                for(int ni=0;ni<4;ni++){
                    MMA(acc[mi][ni], aH[mi], bH[ni]);
                    MMA(acc[mi][ni], aL[mi], bH[ni]);
                    MMA(acc[mi][ni], aH[mi], bL[ni]);
                }
        }
        __syncthreads();
    }
    #pragma unroll
    for(int mi=0;mi<2;mi++){
        int row = m0 + wm*32 + mi*16 + g;
        #pragma unroll
        for(int ni=0;ni<4;ni++){
            int col = n0 + wn*32 + ni*8 + tg*2;
            float* p0 = C + (size_t)row*N + col;
            float* p1 = C + (size_t)(row+8)*N + col;
            if(accumulate){
                p0[0]+=acc[mi][ni][0]; p0[1]+=acc[mi][ni][1];
                p1[0]+=acc[mi][ni][2]; p1[1]+=acc[mi][ni][3];
            } else {
                p0[0]=acc[mi][ni][0]; p0[1]=acc[mi][ni][1];
                p1[0]=acc[mi][ni][2]; p1[1]=acc[mi][ni][3];
            }
        }
    }
}

// ---------------- encoder LSTM pointwise ----------------
__global__ void enc_pw_k(const float* __restrict__ bih, const float* __restrict__ bhh, int t){
    int idx = blockIdx.x*blockDim.x + threadIdx.x;
    if(idx >= BSZ*AD) return;
    int j = idx % AD, b = idx / AD;
    const float* xw = g_xW + ((size_t)b*TT + t)*(4*AD);
    const float* hw = g_hW + (size_t)b*(4*AD);
    float gi = xw[j     ] + hw[j     ] + __ldg(bih+j     ) + __ldg(bhh+j     );
    float gf = xw[j+AD  ] + hw[j+AD  ] + __ldg(bih+j+AD  ) + __ldg(bhh+j+AD  );
    float gg = xw[j+2*AD] + hw[j+2*AD] + __ldg(bih+j+2*AD) + __ldg(bhh+j+2*AD);
    float go = xw[j+3*AD] + hw[j+3*AD] + __ldg(bih+j+3*AD) + __ldg(bhh+j+3*AD);
    float c = sigm(gf)*g_c[idx] + sigm(gi)*tanhf(gg);
    float h = sigm(go)*tanhf(c);
    g_c[idx] = c; g_h[idx] = h;
    g_y8[((size_t)b*TT + t)*AD + j] = h;
}

__global__ void init_enc_k(const float* __restrict__ h0, const float* __restrict__ c0){
    int idx = blockIdx.x*blockDim.x + threadIdx.x;
    if(idx >= BSZ*AD) return;
    g_h[idx] = __ldg(h0 + idx%AD);
    g_c[idx] = __ldg(c0 + idx%AD);
}

__global__ void init_dec_k(){
    int idx = blockIdx.x*blockDim.x + threadIdx.x;
    if(idx >= BSZ*HID) return;
    g_dh[idx] = 0.f; g_dc[idx] = 0.f;
}

// ---------------- enc_score = y8 @ w_e ----------------
__global__ void enc_score_k(const float* __restrict__ att_w){
    int gl = blockIdx.x*blockDim.x + threadIdx.x;
    int row = gl >> 5, lane = gl & 31;
    if(row >= BSZ*TT) return;
    const float* r = g_y8 + (size_t)row*AD;
    const float* we = att_w + HID;
    float s = 0.f;
    for(int k=lane; k<AD; k+=32) s += r[k]*__ldg(we+k);
    #pragma unroll
    for(int o=16;o>0;o>>=1) s += __shfl_xor_sync(0xffffffffu, s, o);
    if(lane==0) g_escore[row] = s;
}

// ---------------- attention: softmax over T + context ----------------
__global__ void attn_k(const float* __restrict__ att_w, const float* __restrict__ att_b){
    int b = blockIdx.x, tid = threadIdx.x;   // 256 threads
    __shared__ float red[256];
    __shared__ float sc[TT];
    float v = (tid<HID) ? g_dh[(size_t)b*HID + tid]*__ldg(att_w+tid) : 0.f;
    red[tid] = v; __syncthreads();
    #pragma unroll
    for(int s=128;s>0;s>>=1){ if(tid<s) red[tid]+=red[tid+s]; __syncthreads(); }
    float hw = red[0] + __ldg(att_b);
    if(tid < TT) sc[tid] = g_escore[b*TT + tid] + hw;
    __syncthreads();
    if(tid < 32){
        float x = sc[tid];
        float mx = x;
        #pragma unroll
        for(int o=16;o>0;o>>=1) mx = fmaxf(mx, __shfl_xor_sync(0xffffffffu, mx, o));
        float e = expf(x - mx);
        float sm = e;
        #pragma unroll
        for(int o=16;o>0;o>>=1) sm += __shfl_xor_sync(0xffffffffu, sm, o);
        sc[tid] = e/sm;
    }
    __syncthreads();
    if(tid < AD){
        const float* y = g_y8 + (size_t)b*TT*AD + tid;
        float s = 0.f;
        #pragma unroll
        for(int t=0;t<TT;t++) s += sc[t]*y[t*AD];
        g_ctx[(size_t)b*AD + tid] = s;
    }
}

// ---------------- decoder LSTM pointwise ----------------
__global__ void dec_pw_k(const float* __restrict__ bih, const float* __restrict__ bhh){
    int idx = blockIdx.x*blockDim.x + threadIdx.x;
    if(idx >= BSZ*HID) return;
    int j = idx % HID, b = idx / HID;
    const float* g = g_gates + (size_t)b*4*HID;
    float gi = g[j      ] + __ldg(bih+j      ) + __ldg(bhh+j      );
    float gf = g[j+HID  ] + __ldg(bih+j+HID  ) + __ldg(bhh+j+HID  );
    float gg = g[j+2*HID] + __ldg(bih+j+2*HID) + __ldg(bhh+j+2*HID);
    float go = g[j+3*HID] + __ldg(bih+j+3*HID) + __ldg(bhh+j+3*HID);
    float c = sigm(gf)*g_dc[idx] + sigm(gi)*tanhf(gg);
    float h = sigm(go)*tanhf(c);
    g_dc[idx] = c; g_dh[idx] = h;
}

// ---------------- output projection ----------------
__global__ void out_k(const float* __restrict__ out_w, const float* __restrict__ out_b,
                      float* __restrict__ out, int step){
    int gl = blockIdx.x*blockDim.x + threadIdx.x;
    int wid = gl >> 5, lane = gl & 31;
    if(wid >= BSZ*VOCAB) return;
    int v = wid % VOCAB, b = wid / VOCAB;
    const float* h = g_dh + (size_t)b*HID;
    const float* w = out_w + (size_t)v*HID;
    float s = 0.f;
    #pragma unroll
    for(int k=lane; k<HID; k+=32) s += h[k]*__ldg(w+k);
    #pragma unroll
    for(int o=16;o>0;o>>=1) s += __shfl_xor_sync(0xffffffffu, s, o);
    if(lane==0) out[(size_t)b*VOCAB*OUT_LEN + v*OUT_LEN + step] = s + __ldg(out_b+v);
}

// ---------------- launch ----------------
extern "C" void kernel_launch(void* const* d_in, const int* in_sizes, int n_in,
                              void* d_out, int out_size){
    const float* x       = (const float*)d_in[0];
    const float* c1w     = (const float*)d_in[1];
    const float* c1b     = (const float*)d_in[2];
    const float* c2w     = (const float*)d_in[3];
    const float* c2b     = (const float*)d_in[4];
    const float* c3w     = (const float*)d_in[5];
    const float* c3b     = (const float*)d_in[6];
    const float* c4w     = (const float*)d_in[7];
    const float* c4b     = (const float*)d_in[8];
    const float* h0      = (const float*)d_in[9];
    const float* c0      = (const float*)d_in[10];
    const float* lstmWih = (const float*)d_in[11];
    const float* lstmWhh = (const float*)d_in[12];
    const float* lstmbih = (const float*)d_in[13];
    const float* lstmbhh = (const float*)d_in[14];
    const float* attw    = (const float*)d_in[15];
    const float* attb    = (const float*)d_in[16];
    const float* decWih  = (const float*)d_in[17];
    const float* decWhh  = (const float*)d_in[18];
    const float* decbih  = (const float*)d_in[19];
    const float* decbhh  = (const float*)d_in[20];
    const float* outw    = (const float*)d_in[21];
    const float* outb    = (const float*)d_in[22];
    float* out = (float*)d_out;

    float *y1,*y2,*y3,*y5,*xW,*h,*hW,*dh,*ctx,*gates;
    cudaGetSymbolAddress((void**)&y1,    g_y1);
    cudaGetSymbolAddress((void**)&y2,    g_y2);
    cudaGetSymbolAddress((void**)&y3,    g_y3);
    cudaGetSymbolAddress((void**)&y5,    g_y5);
    cudaGetSymbolAddress((void**)&xW,    g_xW);
    cudaGetSymbolAddress((void**)&h,     g_h);
    cudaGetSymbolAddress((void**)&hW,    g_hW);
    cudaGetSymbolAddress((void**)&dh,    g_dh);
    cudaGetSymbolAddress((void**)&ctx,   g_ctx);
    cudaGetSymbolAddress((void**)&gates, g_gates);

    // conv stack
    convpool_k<1, 4,384,28,2,1><<<(BSZ*4*192*28+255)/256,256>>>(x,  c1w,c1b, y1);
    convpool_k<4,16,192,28,2,2><<<(BSZ*16*96*14+255)/256,256>>>(y1, c2w,c2b, y2);
    convpool_k<16,16, 96,14,3,2><<<(BSZ*16*32*7+255)/256,256>>>(y2, c3w,c3b, y3);
    conv4_k<<<BSZ,256>>>(y3, c4w, c4b, y5);

    // hoisted encoder input transform: (B*T,224) @ (896,224)^T
    gemm_tc<<<dim3(4*AD/64, BSZ*TT/64), 128>>>(y5, lstmWih, xW, BSZ*TT, 4*AD, AD, 0);

    // encoder LSTM scan
    init_enc_k<<<(BSZ*AD+255)/256,256>>>(h0, c0);
    for(int t=0; t<TT; t++){
        gemm_tc<<<dim3(4*AD/64, BSZ/64), 128>>>(h, lstmWhh, hW, BSZ, 4*AD, AD, 0);
        enc_pw_k<<<(BSZ*AD+255)/256,256>>>(lstmbih, lstmbhh, t);
    }

    // attention precompute + decoder init
    enc_score_k<<<(BSZ*TT*32+255)/256,256>>>(attw);
    init_dec_k<<<(BSZ*HID+255)/256,256>>>();

    // decoder scan
    for(int s=0; s<OUT_LEN; s++){
        attn_k<<<BSZ,256>>>(attw, attb);
        gemm_tc<<<dim3(4*HID/64, BSZ/64), 128>>>(ctx, decWih, gates, BSZ, 4*HID, AD,  0);
        gemm_tc<<<dim3(4*HID/64, BSZ/64), 128>>>(dh,  decWhh, gates, BSZ, 4*HID, HID, 1);
        dec_pw_k<<<(BSZ*HID+255)/256,256>>>(decbih, decbhh);
        out_k<<<(BSZ*VOCAB*32+255)/256,256>>>(outw, outb, out, s);
    }
}

// round 4
// speedup vs baseline: 2.5873x; 2.1355x over previous
#include <cuda_runtime.h>
#include <cuda_bf16.h>
#include <cstdint>

#define BSZ  1024
#define TT   32
#define AD   224
#define HID  256
#define VOCAB 29
#define OUT_LEN 25
#define KCAT 480

// ---------------- scratch ----------------
__device__ float g_y1[BSZ*4*192*28];
__device__ float g_y2[BSZ*16*96*14];
__device__ float g_y3[BSZ*16*32*7];
__device__ float g_y5[BSZ*TT*AD];
__device__ float g_xW[BSZ*TT*4*AD];
__device__ float g_hbuf[2][BSZ*AD];
__device__ float g_c [BSZ*AD];
__device__ float g_y8[BSZ*TT*AD];
__device__ float g_escore[BSZ*TT];
__device__ float g_dh[BSZ*HID];
__device__ float g_dc[BSZ*HID];
__device__ float g_cat[2][BSZ*KCAT];
// pre-split weights (bf16x2 hi/lo packed as u32), gate-interleaved rows
__device__ uint32_t g_WihH[896*112], g_WihL[896*112];
__device__ uint32_t g_WhhH[896*112], g_WhhL[896*112];
__device__ uint32_t g_WdH[1024*240], g_WdL[1024*240];
__device__ float g_bsE[896], g_bsD[1024];

__device__ __forceinline__ float sigm(float x){ return 1.0f/(1.0f+expf(-x)); }
__device__ __forceinline__ float4 ffma4(float4 a, float4 x, float4 w){
    a.x=fmaf(x.x,w.x,a.x); a.y=fmaf(x.y,w.y,a.y);
    a.z=fmaf(x.z,w.z,a.z); a.w=fmaf(x.w,w.w,a.w); return a;
}
__device__ __forceinline__ float hsum4(float4 a){ return a.x+a.y+a.z+a.w; }
__device__ __forceinline__ void splitpair(float x, float y, uint32_t& hi, uint32_t& lo){
    __nv_bfloat162 h = __floats2bfloat162_rn(x, y);
    __nv_bfloat162 l = __floats2bfloat162_rn(x - __bfloat162float(h.x), y - __bfloat162float(h.y));
    hi = *reinterpret_cast<uint32_t*>(&h);
    lo = *reinterpret_cast<uint32_t*>(&l);
}

// =====================  CONV STACK  =====================
// conv1: (1,384,28) -> relu -> pool(2,1) -> (4,192,28)
__global__ __launch_bounds__(256) void conv1_k(const float* __restrict__ x,
        const float* __restrict__ cw, const float* __restrict__ cb, float* __restrict__ out){
    __shared__ float xin[66*30];
    __shared__ float w_s[36];
    __shared__ float b_s[4];
    int b = blockIdx.x/6, pho0 = (blockIdx.x%6)*32;
    int tid = threadIdx.x, lane = tid&31, warp = tid>>5;
    for(int f=tid; f<66*30; f+=256){
        int rr=f/30, cc=f%30;
        int gr=pho0*2-1+rr, gc=cc-1;
        float v=0.f;
        if(gr>=0 && gr<384 && gc>=0 && gc<28) v = x[((size_t)b*384+gr)*28+gc];
        xin[f]=v;
    }
    if(tid<36) w_s[tid]=cw[tid];
    if(tid<4)  b_s[tid]=cb[tid];
    __syncthreads();
    int wo = min(lane,27);
    for(int it=warp; it<128; it+=8){
        int oc=it>>5, ph=it&31;
        float wr[9];
        #pragma unroll
        for(int k=0;k<9;k++) wr[k]=w_s[oc*9+k];
        float bv=b_s[oc], s0=bv, s1=bv;
        #pragma unroll
        for(int kw=0;kw<3;kw++){
            float X[4];
            #pragma unroll
            for(int r=0;r<4;r++) X[r]=xin[(2*ph+r)*30+wo+kw];
            #pragma unroll
            for(int kh=0;kh<3;kh++){
                s0=fmaf(X[kh],  wr[kh*3+kw],s0);
                s1=fmaf(X[kh+1],wr[kh*3+kw],s1);
            }
        }
        float m = fmaxf(fmaxf(s0,0.f), fmaxf(s1,0.f));
        if(lane<28) out[((size_t)(b*4+oc)*192+pho0+ph)*28+wo]=m;
    }
}

// conv2: (4,192,28) -> pool(2,2) -> (16,96,14)
__global__ __launch_bounds__(256) void conv2_k(const float* __restrict__ in,
        const float* __restrict__ cw, const float* __restrict__ cb, float* __restrict__ out){
    __shared__ float4 xin[34*30];
    __shared__ float4 w_s[144];
    __shared__ float  b_s[16];
    int b = blockIdx.x/6, pho0 = (blockIdx.x%6)*16;
    int tid = threadIdx.x, lane = tid&31, warp = tid>>5;
    for(int f=tid; f<34*30; f+=256){
        int rr=f/30, cc=f%30;
        int gr=pho0*2-1+rr, gc=cc-1;
        float4 v={0,0,0,0};
        if(gr>=0 && gr<192 && gc>=0 && gc<28){
            const float* p = in + ((size_t)b*4*192+gr)*28+gc;
            v.x=p[0]; v.y=p[192*28]; v.z=p[2*192*28]; v.w=p[3*192*28];
        }
        xin[f]=v;
    }
    for(int f=tid; f<144; f+=256){
        int oc=f/9, k=f%9;
        float4 v; v.x=cw[(oc*4+0)*9+k]; v.y=cw[(oc*4+1)*9+k];
                  v.z=cw[(oc*4+2)*9+k]; v.w=cw[(oc*4+3)*9+k];
        w_s[f]=v;
    }
    if(tid<16) b_s[tid]=cb[tid];
    __syncthreads();
    int wc = min(lane,27);
    for(int it=warp; it<128; it+=8){
        int oc=it>>3, pp=it&7;
        float4 wr[9];
        #pragma unroll
        for(int k=0;k<9;k++) wr[k]=w_s[oc*9+k];
        float bv=b_s[oc];
        float4 a0={0,0,0,0},a1=a0,a2=a0,a3=a0;
        #pragma unroll
        for(int kw=0;kw<3;kw++){
            float4 X[6];
            #pragma unroll
            for(int r=0;r<6;r++) X[r]=xin[(pp*4+r)*30+wc+kw];
            #pragma unroll
            for(int kh=0;kh<3;kh++){
                float4 w=wr[kh*3+kw];
                a0=ffma4(a0,X[kh],w); a1=ffma4(a1,X[kh+1],w);
                a2=ffma4(a2,X[kh+2],w); a3=ffma4(a3,X[kh+3],w);
            }
        }
        float s0=hsum4(a0)+bv, s1=hsum4(a1)+bv, s2=hsum4(a2)+bv, s3=hsum4(a3)+bv;
        float p0=fmaxf(fmaxf(s0,0.f),fmaxf(s1,0.f));
        float p1=fmaxf(fmaxf(s2,0.f),fmaxf(s3,0.f));
        float q0=fmaxf(p0, __shfl_down_sync(0xffffffffu,p0,1));
        float q1=fmaxf(p1, __shfl_down_sync(0xffffffffu,p1,1));
        if(!(lane&1) && lane<28){
            int wo=wc>>1;
            out[((size_t)(b*16+oc)*96+pho0+2*pp+0)*14+wo]=q0;
            out[((size_t)(b*16+oc)*96+pho0+2*pp+1)*14+wo]=q1;
        }
    }
}

// conv3: (16,96,14) -> pool(3,2) -> (16,32,7)
__global__ __launch_bounds__(256) void conv3_k(const float* __restrict__ in,
        const float* __restrict__ cw, const float* __restrict__ cb, float* __restrict__ out){
    __shared__ float4 xin[4*26*16];
    __shared__ float4 w_s[576];
    __shared__ float  b_s[16];
    int b = blockIdx.x>>2, pho0 = (blockIdx.x&3)*8;
    int tid = threadIdx.x, lane = tid&31, warp = tid>>5;
    for(int f=tid; f<4*26*16; f+=256){
        int icg=f/(26*16), rr=(f/16)%26, cc=f%16;
        int gr=pho0*3-1+rr, gc=cc-1;
        float4 v={0,0,0,0};
        if(gr>=0 && gr<96 && gc>=0 && gc<14){
            const float* p = in + ((size_t)(b*16+icg*4)*96+gr)*14+gc;
            v.x=p[0]; v.y=p[96*14]; v.z=p[2*96*14]; v.w=p[3*96*14];
        }
        xin[f]=v;
    }
    for(int f=tid; f<576; f+=256){
        int oc=f/36, icg=(f/9)%4, k=f%9;
        float4 v;
        v.x=cw[(oc*16+icg*4+0)*9+k]; v.y=cw[(oc*16+icg*4+1)*9+k];
        v.z=cw[(oc*16+icg*4+2)*9+k]; v.w=cw[(oc*16+icg*4+3)*9+k];
        w_s[f]=v;
    }
    if(tid<16) b_s[tid]=cb[tid];
    __syncthreads();
    int half = lane>>4;
    int wc = min(lane&15, 13);
    for(int ib=warp; ib<64; ib+=8){
        int item = ib*2+half;
        int oc=item>>3, ph=item&7;
        float4 a0={0,0,0,0},a1=a0,a2=a0;
        #pragma unroll
        for(int icg=0;icg<4;icg++){
            float4 wr[9];
            #pragma unroll
            for(int k=0;k<9;k++) wr[k]=w_s[(oc*4+icg)*9+k];
            #pragma unroll
            for(int kw=0;kw<3;kw++){
                float4 X[5];
                #pragma unroll
                for(int r=0;r<5;r++) X[r]=xin[(icg*26+3*ph+r)*16+wc+kw];
                #pragma unroll
                for(int kh=0;kh<3;kh++){
                    float4 w=wr[kh*3+kw];
                    a0=ffma4(a0,X[kh],w); a1=ffma4(a1,X[kh+1],w); a2=ffma4(a2,X[kh+2],w);
                }
            }
        }
        float bv=b_s[oc];
        float s0=fmaxf(hsum4(a0)+bv,0.f), s1=fmaxf(hsum4(a1)+bv,0.f), s2=fmaxf(hsum4(a2)+bv,0.f);
        float v=fmaxf(fmaxf(s0,s1),s2);
        float o=fmaxf(v, __shfl_down_sync(0xffffffffu,v,1));
        if(!(lane&1) && (lane&15)<14)
            out[((size_t)(b*16+oc)*32+pho0+ph)*7+(wc>>1)]=o;
    }
}

// conv4: (16,32,7)->(32,32,7), writes y5[b][h][w*32+oc]
__global__ __launch_bounds__(256) void conv4_k(const float* __restrict__ in,
        const float* __restrict__ cw, const float* __restrict__ cb, float* __restrict__ out){
    __shared__ float4 xin[4*34*9];
    __shared__ float4 w_s[1152];
    __shared__ float  b_s[32];
    int b = blockIdx.x;
    int tid = threadIdx.x, lane = tid&31, warp = tid>>5;
    for(int f=tid; f<4*34*9; f+=256){
        int icg=f/(34*9), rr=(f/9)%34, cc=f%9;
        int gr=rr-1, gc=cc-1;
        float4 v={0,0,0,0};
        if(gr>=0 && gr<32 && gc>=0 && gc<7){
            const float* p = in + ((size_t)(b*16+icg*4)*32+gr)*7+gc;
            v.x=p[0]; v.y=p[32*7]; v.z=p[2*32*7]; v.w=p[3*32*7];
        }
        xin[f]=v;
    }
    for(int f=tid; f<1152; f+=256){
        int oc=f/36, icg=(f/9)%4, k=f%9;
        float4 v;
        v.x=cw[(oc*16+icg*4+0)*9+k]; v.y=cw[(oc*16+icg*4+1)*9+k];
        v.z=cw[(oc*16+icg*4+2)*9+k]; v.w=cw[(oc*16+icg*4+3)*9+k];
        w_s[f]=v;
    }
    if(tid<32) b_s[tid]=cb[tid];
    __syncthreads();
    int quarter = lane>>3;
    int wc = min(lane&7, 6);
    for(int ib=warp; ib<64; ib+=8){
        int item = ib*4+quarter;
        int oc=item>>3, hq=item&7;
        float4 ac[4]={{0,0,0,0},{0,0,0,0},{0,0,0,0},{0,0,0,0}};
        #pragma unroll
        for(int icg=0;icg<4;icg++){
            float4 wr[9];
            #pragma unroll
            for(int k=0;k<9;k++) wr[k]=w_s[(oc*4+icg)*9+k];
            #pragma unroll
            for(int kw=0;kw<3;kw++){
                float4 X[6];
                #pragma unroll
                for(int r=0;r<6;r++) X[r]=xin[(icg*34+4*hq+r)*9+wc+kw];
                #pragma unroll
                for(int kh=0;kh<3;kh++){
                    float4 w=wr[kh*3+kw];
                    #pragma unroll
                    for(int r=0;r<4;r++) ac[r]=ffma4(ac[r],X[r+kh],w);
                }
            }
        }
        float bv=b_s[oc];
        #pragma unroll
        for(int r=0;r<4;r++){
            float s=fmaxf(hsum4(ac[r])+bv,0.f);
            if((lane&7)<7)
                out[((size_t)b*32+hq*4+r)*224+wc*32+oc]=s;
        }
    }
}

// =====================  weight prep  =====================
// split W[N][Ksrc] -> u32 hi/lo with gate-interleaved row reorder (n'=j*4+g)
__global__ void split_w_k(const float* __restrict__ W, uint32_t* __restrict__ Wh,
        uint32_t* __restrict__ Wl, int N, int Ksrc, int kstride, int gatesize){
    int idx = blockIdx.x*blockDim.x+threadIdx.x;
    int kp2 = Ksrc>>1;
    if(idx >= N*kp2) return;
    int kp = idx%kp2, np = idx/kp2;
    int srow = np;
    if(gatesize>0){ int j=np>>2, g=np&3; srow = g*gatesize+j; }
    float x = W[(size_t)srow*Ksrc+2*kp], y = W[(size_t)srow*Ksrc+2*kp+1];
    uint32_t h,l; splitpair(x,y,h,l);
    Wh[(size_t)np*kstride+kp]=h; Wl[(size_t)np*kstride+kp]=l;
}
__global__ void bsum_k(const float* __restrict__ bih, const float* __restrict__ bhh,
                       float* __restrict__ bs, int N, int gatesize){
    int np = blockIdx.x*blockDim.x+threadIdx.x;
    if(np>=N) return;
    int j=np>>2, g=np&3, s=g*gatesize+j;
    bs[np] = bih[s]+bhh[s];
}

// =====================  fused tensor-core GEMM  =====================
// C[M,N] = A[M,K] @ B^T ; B pre-split bf16 hi/lo. MODE 0: store C.
// MODE 1: encoder LSTM epilogue (gates interleaved). MODE 2: decoder LSTM epilogue.
#define SAU 17

#define MMA(c, a, b) asm volatile( \
    "mma.sync.aligned.m16n8k16.row.col.f32.bf16.bf16.f32 " \
    "{%0,%1,%2,%3},{%4,%5,%6,%7},{%8,%9},{%0,%1,%2,%3};" \
    : "+f"(c[0]),"+f"(c[1]),"+f"(c[2]),"+f"(c[3]) \
    : "r"(a[0]),"r"(a[1]),"r"(a[2]),"r"(a[3]),"r"(b[0]),"r"(b[1]))

template<int MODE, int K, int KSU, int NCOLS>
__global__ __launch_bounds__(128) void gemm_f(const float* __restrict__ A,
        const uint32_t* __restrict__ BhG, const uint32_t* __restrict__ BlG,
        float* __restrict__ Cout, const float* __restrict__ bsum,
        float* __restrict__ hout, int t){
    __shared__ uint32_t Ah[64*SAU], Al[64*SAU], Bh[64*SAU], Bl[64*SAU];
    __shared__ float cs[64*66];
    int tid=threadIdx.x;
    int m0=blockIdx.y*64, n0=blockIdx.x*64;
    int warp=tid>>5, lane=tid&31;
    int wm=warp>>1, wn=warp&1;
    int g=lane>>2, tg=lane&3;
    float acc[2][4][4];
    #pragma unroll
    for(int mi=0;mi<2;mi++)
        #pragma unroll
        for(int ni=0;ni<4;ni++)
            #pragma unroll
            for(int r=0;r<4;r++) acc[mi][ni][r]=0.f;

    int lr=tid>>1, lk=(tid&1)*16, lkp=(tid&1)*8;

    for(int k0=0;k0<K;k0+=32){
        const float* pa = A + (size_t)(m0+lr)*K + k0+lk;
        #pragma unroll
        for(int q=0;q<4;q++){
            float4 a = *(const float4*)(pa + q*4);
            uint32_t h0,l0,h1,l1;
            splitpair(a.x,a.y,h0,l0); splitpair(a.z,a.w,h1,l1);
            Ah[lr*SAU+lkp+q*2  ]=h0; Al[lr*SAU+lkp+q*2  ]=l0;
            Ah[lr*SAU+lkp+q*2+1]=h1; Al[lr*SAU+lkp+q*2+1]=l1;
        }
        const uint32_t* pbh = BhG + (size_t)(n0+lr)*KSU + (k0>>1) + lkp;
        const uint32_t* pbl = BlG + (size_t)(n0+lr)*KSU + (k0>>1) + lkp;
        uint4 bh0=*(const uint4*)pbh, bh1=*(const uint4*)(pbh+4);
        uint4 bl0=*(const uint4*)pbl, bl1=*(const uint4*)(pbl+4);
        Bh[lr*SAU+lkp+0]=bh0.x; Bh[lr*SAU+lkp+1]=bh0.y; Bh[lr*SAU+lkp+2]=bh0.z; Bh[lr*SAU+lkp+3]=bh0.w;
        Bh[lr*SAU+lkp+4]=bh1.x; Bh[lr*SAU+lkp+5]=bh1.y; Bh[lr*SAU+lkp+6]=bh1.z; Bh[lr*SAU+lkp+7]=bh1.w;
        Bl[lr*SAU+lkp+0]=bl0.x; Bl[lr*SAU+lkp+1]=bl0.y; Bl[lr*SAU+lkp+2]=bl0.z; Bl[lr*SAU+lkp+3]=bl0.w;
        Bl[lr*SAU+lkp+4]=bl1.x; Bl[lr*SAU+lkp+5]=bl1.y; Bl[lr*SAU+lkp+6]=bl1.z; Bl[lr*SAU+lkp+7]=bl1.w;
        __syncthreads();
        #pragma unroll
        for(int kk=0;kk<2;kk++){
            uint32_t aH[2][4], aL[2][4], bH[4][2], bL[4][2];
            int kp = kk*8+tg;
            #pragma unroll
            for(int mi=0;mi<2;mi++){
                int r0 = wm*32+mi*16+g;
                aH[mi][0]=Ah[ r0   *SAU+kp  ]; aH[mi][1]=Ah[(r0+8)*SAU+kp  ];
                aH[mi][2]=Ah[ r0   *SAU+kp+4]; aH[mi][3]=Ah[(r0+8)*SAU+kp+4];
                aL[mi][0]=Al[ r0   *SAU+kp  ]; aL[mi][1]=Al[(r0+8)*SAU+kp  ];
                aL[mi][2]=Al[ r0   *SAU+kp+4]; aL[mi][3]=Al[(r0+8)*SAU+kp+4];
            }
            #pragma unroll
            for(int ni=0;ni<4;ni++){
                int c0 = wn*32+ni*8+g;
                bH[ni][0]=Bh[c0*SAU+kp]; bH[ni][1]=Bh[c0*SAU+kp+4];
                bL[ni][0]=Bl[c0*SAU+kp]; bL[ni][1]=Bl[c0*SAU+kp+4];
            }
            #pragma unroll
            for(int mi=0;mi<2;mi++)
                #pragma unroll
                for(int ni=0;ni<4;ni++){
                    MMA(acc[mi][ni], aH[mi], bH[ni]);
                    MMA(acc[mi][ni], aL[mi], bH[ni]);
                    MMA(acc[mi][ni], aH[mi], bL[ni]);
                }
        }
        __syncthreads();
    }

    if(MODE==0){
        #pragma unroll
        for(int mi=0;mi<2;mi++){
            int row = m0+wm*32+mi*16+g;
            #pragma unroll
            for(int ni=0;ni<4;ni++){
                int col = n0+wn*32+ni*8+tg*2;
                float* p0 = Cout + (size_t)row*NCOLS + col;
                float* p1 = Cout + (size_t)(row+8)*NCOLS + col;
                p0[0]=acc[mi][ni][0]; p0[1]=acc[mi][ni][1];
                p1[0]=acc[mi][ni][2]; p1[1]=acc[mi][ni][3];
            }
        }
        return;
    }
    // stage acc tile into smem
    #pragma unroll
    for(int mi=0;mi<2;mi++){
        int r0 = wm*32+mi*16+g;
        #pragma unroll
        for(int ni=0;ni<4;ni++){
            int c0c = wn*32+ni*8+tg*2;
            cs[r0*66+c0c]=acc[mi][ni][0];     cs[r0*66+c0c+1]=acc[mi][ni][1];
            cs[(r0+8)*66+c0c]=acc[mi][ni][2]; cs[(r0+8)*66+c0c+1]=acc[mi][ni][3];
        }
    }
    __syncthreads();
    #pragma unroll
    for(int p=tid;p<1024;p+=128){
        int jj = p&15, m = p>>4;
        int b = m0+m, col = n0+4*jj, j = (n0>>2)+jj;
        float gi,gf,gg,go;
        if(MODE==1){
            const float* xw = g_xW + ((size_t)b*TT+t)*896 + col;
            gi = cs[m*66+4*jj+0] + xw[0] + __ldg(bsum+col+0);
            gf = cs[m*66+4*jj+1] + xw[1] + __ldg(bsum+col+1);
            gg = cs[m*66+4*jj+2] + xw[2] + __ldg(bsum+col+2);
            go = cs[m*66+4*jj+3] + xw[3] + __ldg(bsum+col+3);
            float c = sigm(gf)*g_c[(size_t)b*AD+j] + sigm(gi)*tanhf(gg);
            float h = sigm(go)*tanhf(c);
            g_c[(size_t)b*AD+j]=c;
            hout[(size_t)b*AD+j]=h;
            g_y8[((size_t)b*TT+t)*AD+j]=h;
        } else {
            gi = cs[m*66+4*jj+0] + __ldg(bsum+col+0);
            gf = cs[m*66+4*jj+1] + __ldg(bsum+col+1);
            gg = cs[m*66+4*jj+2] + __ldg(bsum+col+2);
            go = cs[m*66+4*jj+3] + __ldg(bsum+col+3);
            float c = sigm(gf)*g_dc[(size_t)b*HID+j] + sigm(gi)*tanhf(gg);
            float h = sigm(go)*tanhf(c);
            g_dc[(size_t)b*HID+j]=c;
            g_dh[(size_t)b*HID+j]=h;
            Cout[(size_t)b*KCAT + AD + j]=h;   // dh slot of next cat buffer
        }
    }
}

// =====================  small kernels  =====================
__global__ void init_enc_k(const float* __restrict__ h0, const float* __restrict__ c0,
                           float* __restrict__ hbuf0){
    int idx = blockIdx.x*blockDim.x+threadIdx.x;
    if(idx>=BSZ*AD) return;
    hbuf0[idx]=__ldg(h0+idx%AD);
    g_c[idx]=__ldg(c0+idx%AD);
}
__global__ void init_dec_k(float* __restrict__ cat0){
    int idx = blockIdx.x*blockDim.x+threadIdx.x;
    if(idx<BSZ*HID){ g_dh[idx]=0.f; g_dc[idx]=0.f; }
    if(idx<BSZ*KCAT) cat0[idx]=0.f;
}
__global__ void enc_score_k(const float* __restrict__ att_w){
    int gl = blockIdx.x*blockDim.x+threadIdx.x;
    int row = gl>>5, lane = gl&31;
    if(row>=BSZ*TT) return;
    const float* r = g_y8 + (size_t)row*AD;
    const float* we = att_w + HID;
    float s=0.f;
    for(int k=lane;k<AD;k+=32) s += r[k]*__ldg(we+k);
    #pragma unroll
    for(int o=16;o>0;o>>=1) s += __shfl_xor_sync(0xffffffffu,s,o);
    if(lane==0) g_escore[row]=s;
}
__global__ void attn_k(const float* __restrict__ att_w, const float* __restrict__ att_b,
                       float* __restrict__ catbuf){
    int b = blockIdx.x, tid = threadIdx.x;
    __shared__ float red[256];
    __shared__ float sc[TT];
    float v = (tid<HID) ? g_dh[(size_t)b*HID+tid]*__ldg(att_w+tid) : 0.f;
    red[tid]=v; __syncthreads();
    #pragma unroll
    for(int s=128;s>0;s>>=1){ if(tid<s) red[tid]+=red[tid+s]; __syncthreads(); }
    float hw = red[0]+__ldg(att_b);
    if(tid<TT) sc[tid] = g_escore[b*TT+tid]+hw;
    __syncthreads();
    if(tid<32){
        float x=sc[tid], mx=x;
        #pragma unroll
        for(int o=16;o>0;o>>=1) mx=fmaxf(mx,__shfl_xor_sync(0xffffffffu,mx,o));
        float e=expf(x-mx), sm=e;
        #pragma unroll
        for(int o=16;o>0;o>>=1) sm+=__shfl_xor_sync(0xffffffffu,sm,o);
        sc[tid]=e/sm;
    }
    __syncthreads();
    if(tid<AD){
        const float* y = g_y8 + (size_t)b*TT*AD + tid;
        float s=0.f;
        #pragma unroll
        for(int t=0;t<TT;t++) s += sc[t]*y[t*AD];
        catbuf[(size_t)b*KCAT+tid]=s;
    }
}
__global__ void out_k(const float* __restrict__ out_w, const float* __restrict__ out_b,
                      float* __restrict__ out, int step){
    int gl = blockIdx.x*blockDim.x+threadIdx.x;
    int wid = gl>>5, lane = gl&31;
    if(wid>=BSZ*VOCAB) return;
    int v = wid%VOCAB, b = wid/VOCAB;
    const float* h = g_dh + (size_t)b*HID;
    const float* w = out_w + (size_t)v*HID;
    float s=0.f;
    #pragma unroll
    for(int k=lane;k<HID;k+=32) s += h[k]*__ldg(w+k);
    #pragma unroll
    for(int o=16;o>0;o>>=1) s += __shfl_xor_sync(0xffffffffu,s,o);
    if(lane==0) out[(size_t)b*VOCAB*OUT_LEN + v*OUT_LEN + step] = s + __ldg(out_b+v);
}

// =====================  launch  =====================
extern "C" void kernel_launch(void* const* d_in, const int* in_sizes, int n_in,
                              void* d_out, int out_size){
    const float* x       = (const float*)d_in[0];
    const float* c1w     = (const float*)d_in[1];
    const float* c1b     = (const float*)d_in[2];
    const float* c2w     = (const float*)d_in[3];
    const float* c2b     = (const float*)d_in[4];
    const float* c3w     = (const float*)d_in[5];
    const float* c3b     = (const float*)d_in[6];
    const float* c4w     = (const float*)d_in[7];
    const float* c4b     = (const float*)d_in[8];
    const float* h0      = (const float*)d_in[9];
    const float* c0      = (const float*)d_in[10];
    const float* lstmWih = (const float*)d_in[11];
    const float* lstmWhh = (const float*)d_in[12];
    const float* lstmbih = (const float*)d_in[13];
    const float* lstmbhh = (const float*)d_in[14];
    const float* attw    = (const float*)d_in[15];
    const float* attb    = (const float*)d_in[16];
    const float* decWih  = (const float*)d_in[17];
    const float* decWhh  = (const float*)d_in[18];
    const float* decbih  = (const float*)d_in[19];
    const float* decbhh  = (const float*)d_in[20];
    const float* outw    = (const float*)d_in[21];
    const float* outb    = (const float*)d_in[22];
    float* out = (float*)d_out;

    float *y1,*y2,*y3,*y5,*xW,*hbuf,*cat,*bsE,*bsD;
    uint32_t *WihH,*WihL,*WhhH,*WhhL,*WdH,*WdL;
    cudaGetSymbolAddress((void**)&y1,  g_y1);
    cudaGetSymbolAddress((void**)&y2,  g_y2);
    cudaGetSymbolAddress((void**)&y3,  g_y3);
    cudaGetSymbolAddress((void**)&y5,  g_y5);
    cudaGetSymbolAddress((void**)&xW,  g_xW);
    cudaGetSymbolAddress((void**)&hbuf,g_hbuf);
    cudaGetSymbolAddress((void**)&cat, g_cat);
    cudaGetSymbolAddress((void**)&bsE, g_bsE);
    cudaGetSymbolAddress((void**)&bsD, g_bsD);
    cudaGetSymbolAddress((void**)&WihH,g_WihH);
    cudaGetSymbolAddress((void**)&WihL,g_WihL);
    cudaGetSymbolAddress((void**)&WhhH,g_WhhH);
    cudaGetSymbolAddress((void**)&WhhL,g_WhhL);
    cudaGetSymbolAddress((void**)&WdH, g_WdH);
    cudaGetSymbolAddress((void**)&WdL, g_WdL);
    float* hb[2] = { hbuf, hbuf + BSZ*AD };
    float* cb[2] = { cat,  cat  + BSZ*KCAT };

    // weight prep
    split_w_k<<<(896*112+255)/256,256>>>(lstmWih, WihH, WihL, 896, 224, 112, 224);
    split_w_k<<<(896*112+255)/256,256>>>(lstmWhh, WhhH, WhhL, 896, 224, 112, 224);
    split_w_k<<<(1024*112+255)/256,256>>>(decWih, WdH,     WdL,     1024, 224, 240, 256);
    split_w_k<<<(1024*128+255)/256,256>>>(decWhh, WdH+112, WdL+112, 1024, 256, 240, 256);
    bsum_k<<<(896+255)/256,256>>>(lstmbih, lstmbhh, bsE, 896, 224);
    bsum_k<<<(1024+255)/256,256>>>(decbih, decbhh, bsD, 1024, 256);

    // conv stack
    conv1_k<<<BSZ*6,256>>>(x,  c1w, c1b, y1);
    conv2_k<<<BSZ*6,256>>>(y1, c2w, c2b, y2);
    conv3_k<<<BSZ*4,256>>>(y2, c3w, c3b, y3);
    conv4_k<<<BSZ,  256>>>(y3, c4w, c4b, y5);

    // hoisted xW = y5 @ Wih^T (interleaved columns)
    gemm_f<0,224,112,896><<<dim3(14,512),128>>>(y5, WihH, WihL, xW, nullptr, nullptr, 0);

    // encoder scan (fused GEMM + LSTM cell)
    init_enc_k<<<(BSZ*AD+255)/256,256>>>(h0, c0, hb[0]);
    for(int t=0;t<TT;t++)
        gemm_f<1,224,112,896><<<dim3(14,16),128>>>(hb[t&1], WhhH, WhhL,
                nullptr, bsE, hb[(t+1)&1], t);

    // attention precompute + decoder init
    enc_score_k<<<(BSZ*TT*32+255)/256,256>>>(attw);
    init_dec_k<<<(BSZ*KCAT+255)/256,256>>>(cb[0]);

    // decoder scan (attn -> fused GEMM+LSTM -> out)
    for(int s=0;s<OUT_LEN;s++){
        attn_k<<<BSZ,256>>>(attw, attb, cb[s&1]);
        gemm_f<2,480,240,1024><<<dim3(16,16),128>>>(cb[s&1], WdH, WdL,
                cb[(s+1)&1], bsD, nullptr, 0);
        out_k<<<(BSZ*VOCAB*32+255)/256,256>>>(outw, outb, out, s);
    }
}